// round 9
// baseline (speedup 1.0000x reference)
#include <cuda_runtime.h>
#include <cuda_bf16.h>

// ---------------------------------------------------------------------------
// LSTM-VAE forward.  B=64, T=1000, IN=8, H=512, Z4=2048, LAT=128
// Output layout: [recon (B,T,IN) | mu (B,LAT) | logvar (B,LAT)]
// ---------------------------------------------------------------------------

#define Bz   64
#define Tz   1000
#define INz  8
#define Hz   512
#define Z4z  2048
#define LATz 128

// ------------------------- scratch (__device__ globals) --------------------
__device__ float g_e[Bz * Tz];                       // EMA channel      (B,T)
__device__ float g_hin[(size_t)Tz * Hz * Bz];        // enc input        (T,H,B)
__device__ float g_xg[(size_t)Tz * Z4z * Bz];        // enc gate preacts (T,Z4,B)
__device__ float g_xgdec[Z4z * Bz];                  // dec gate preacts (Z4,B)
__device__ float g_hbuf[2][Hz * Bz];                 // h double buffer  ([k][b])
__device__ float g_hs[(size_t)Tz * Hz * Bz];         // dec hidden seq   (T,H,B)
__device__ float g_z[Bz * LATz];
__device__ float g_d[Bz * Hz];
__device__ unsigned g_barrier;

__device__ __forceinline__ float sigf(float x) { return 1.f / (1.f + __expf(-x)); }

// --------------------------------- EMA -------------------------------------
__global__ void k_ema(const float* __restrict__ x) {
    int b = threadIdx.x;                       // 64 threads
    float e = x[((size_t)b * Tz) * INz + 1];
    g_e[b * Tz] = e;
#pragma unroll 4
    for (int t = 1; t < Tz; ++t) {
        float v = x[((size_t)b * Tz + t) * INz + 1];
        e = 0.1f * v + 0.9f * e;
        g_e[b * Tz + t] = e;
    }
}

// ---------------- input FC + ReLU + positional encoding --------------------
// hin[t][h][b] = relu(W x_mod[b,t,:] + b)[h] + pe[t][h]
__global__ void __launch_bounds__(256) k_hin(const float* __restrict__ x,
                                             const float* __restrict__ w,
                                             const float* __restrict__ bias) {
    int t = blockIdx.x, ht = blockIdx.y * 64;
    __shared__ float s_x[64][8];
    __shared__ float s_w[64][8];
    __shared__ float s_b[64];
    __shared__ float s_pe[64];
    int tid = threadIdx.x;

    for (int i = tid; i < 512; i += 256) {
        int bb = i >> 3, ii = i & 7;
        float v = x[((size_t)bb * Tz + t) * INz + ii];
        if (ii == 1) v = g_e[bb * Tz + t];
        s_x[bb][ii] = v;
    }
    for (int i = tid; i < 512; i += 256) {
        int hh = i >> 3, ii = i & 7;
        s_w[hh][ii] = w[(ht + hh) * INz + ii];
    }
    if (tid < 64) {
        int h = ht + tid;
        s_b[tid] = bias[h];
        int j = h >> 1;
        float div = __expf(-(float)(2 * j) * (9.2103403719761836f / 512.f));
        float ang = (float)t * div;
        s_pe[tid] = 0.1f * ((h & 1) ? cosf(ang) : sinf(ang));
    }
    __syncthreads();

    int hh = tid >> 2, bq = tid & 3;
    for (int q = 0; q < 16; ++q) {
        int bb = bq * 16 + q;
        float a = s_b[hh];
#pragma unroll
        for (int i = 0; i < 8; ++i) a += s_w[hh][i] * s_x[bb][i];
        a = fmaxf(a, 0.f) + s_pe[hh];
        g_hin[((size_t)t * Hz + ht + hh) * Bz + bb] = a;
    }
}

// ------------- encoder gate preactivations: xg = hin @ w_ihT + b -----------
// out xg[t][g][b].  grid (T, Z4/128), 256 thr.  block: 128 g x 64 b, k=512.
__global__ void __launch_bounds__(256) k_xg(const float* __restrict__ wih,
                                            const float* __restrict__ bih,
                                            const float* __restrict__ bhh) {
    int t = blockIdx.x, g0 = blockIdx.y * 128;
    __shared__ float s_w[128 * 36];     // [r][k] pad 36
    __shared__ float s_hn[32 * 64];     // [kk][b]
    int tid = threadIdx.x;
    int rg = tid >> 4, bg = tid & 15;   // rg: 16 groups of 8 rows, bg: 16 groups of 4 b
    float4 acc[8];
#pragma unroll
    for (int r = 0; r < 8; ++r) acc[r] = make_float4(0.f, 0.f, 0.f, 0.f);

    for (int kc = 0; kc < Hz; kc += 32) {
        for (int i = tid; i < 1024; i += 256) {      // 128 rows x 8 float4
            int r = i >> 3, k4 = i & 7;
            float4 v = *(const float4*)&wih[(size_t)(g0 + r) * Hz + kc + k4 * 4];
            *(float4*)&s_w[r * 36 + k4 * 4] = v;
        }
        for (int i = tid; i < 512; i += 256) {       // 32 kk x 16 float4
            int kk = i >> 4, b4 = i & 15;
            *(float4*)&s_hn[kk * 64 + b4 * 4] =
                *(const float4*)&g_hin[((size_t)t * Hz + kc + kk) * Bz + b4 * 4];
        }
        __syncthreads();
#pragma unroll 8
        for (int kk = 0; kk < 32; ++kk) {
            float4 hv = *(float4*)&s_hn[kk * 64 + bg * 4];
#pragma unroll
            for (int r = 0; r < 8; ++r) {
                float wv = s_w[(rg * 8 + r) * 36 + kk];
                acc[r].x += wv * hv.x; acc[r].y += wv * hv.y;
                acc[r].z += wv * hv.z; acc[r].w += wv * hv.w;
            }
        }
        __syncthreads();
    }
#pragma unroll
    for (int r = 0; r < 8; ++r) {
        int g = g0 + rg * 8 + r;
        float bb = bih[g] + bhh[g];
        acc[r].x += bb; acc[r].y += bb; acc[r].z += bb; acc[r].w += bb;
        *(float4*)&g_xg[((size_t)t * Z4z + g) * Bz + bg * 4] = acc[r];
    }
}

// --------------------------- reset barrier + h ------------------------------
__global__ void k_reset() {
    int i = blockIdx.x * blockDim.x + threadIdx.x;
    if (i == 0) g_barrier = 0u;
    if (i < Hz * Bz) { g_hbuf[0][i] = 0.f; g_hbuf[1][i] = 0.f; }
}

// --------------------------- persistent LSTM recurrence ---------------------
// 128 blocks, 1/SM.  Block owns 4 hidden units (16 gate rows) for all 64 batch.
// Local gate row r = gtype*4 + ui  -> global row gtype*512 + (4*bid + ui).
#define WP 516
#define SMEM_RECUR ((32768 + 16 * WP + 4096) * 4)

#define FMASTEP(WX, HV)                                                         \
    a0.x += wv0.WX * HV.x; a0.y += wv0.WX * HV.y; a0.z += wv0.WX * HV.z; a0.w += wv0.WX * HV.w; \
    a1.x += wv1.WX * HV.x; a1.y += wv1.WX * HV.y; a1.z += wv1.WX * HV.z; a1.w += wv1.WX * HV.w; \
    a2.x += wv2.WX * HV.x; a2.y += wv2.WX * HV.y; a2.z += wv2.WX * HV.z; a2.w += wv2.WX * HV.w; \
    a3.x += wv3.WX * HV.x; a3.y += wv3.WX * HV.y; a3.z += wv3.WX * HV.z; a3.w += wv3.WX * HV.w;

__global__ void __launch_bounds__(256, 1) k_recur(const float* __restrict__ whh,
                                                  int phase) {
    const float* xg = phase ? g_xgdec : g_xg;
    const size_t tstr = phase ? 0 : (size_t)Z4z * Bz;
    float* hs = phase ? g_hs : (float*)0;

    extern __shared__ float sm[];
    float* s_h = sm;                    // [k][b] 512*64
    float* s_w = sm + 32768;            // [16][WP]
    float* s_p = s_w + 16 * WP;         // partials [ks][rg][bg][r][bi] = 4096

    const int tid = threadIdx.x, bid = blockIdx.x;

    // stage this block's 16 w_hh rows into SMEM (once)
    for (int i = tid; i < 16 * Hz; i += 256) {
        int r = i >> 9, k = i & 511;
        int grow = ((r >> 2) << 9) + bid * 4 + (r & 3);
        s_w[r * WP + k] = whh[(size_t)grow * Hz + k];
    }

    // mapping A (compute): ksl = k-slice, rg = row group, bg = batch group
    const int ksl = tid >> 6, rg = (tid >> 4) & 3, bg = tid & 15;
    // mapping B (cell update): (ui, bb)
    const int ui = tid >> 6, bb = tid & 63;
    const int u_glob = bid * 4 + ui;
    float c = 0.f;
    __syncthreads();

    for (int t = 0; t < Tz; ++t) {
        // prefetch gate preactivations for this (unit, batch)
        const float* xp = xg + (size_t)t * tstr;
        float xa0 = __ldg(&xp[(0 * Hz + u_glob) * Bz + bb]);
        float xa1 = __ldg(&xp[(1 * Hz + u_glob) * Bz + bb]);
        float xa2 = __ldg(&xp[(2 * Hz + u_glob) * Bz + bb]);
        float xa3 = __ldg(&xp[(3 * Hz + u_glob) * Bz + bb]);

        // stage h_{t-1} (L2 -> SMEM), .cg to bypass stale L1
        {
            const float4* src = (const float4*)g_hbuf[t & 1];
            float4* dst = (float4*)s_h;
#pragma unroll
            for (int i = 0; i < 32; ++i) dst[tid + (i << 8)] = __ldcg(&src[tid + (i << 8)]);
        }
        __syncthreads();

        // compute: 4 rows x 4 batch tile over k-slice of 128
        float4 a0 = make_float4(0.f,0.f,0.f,0.f), a1 = a0, a2 = a0, a3 = a0;
        {
            const float* w0 = s_w + (rg * 4 + 0) * WP;
            const float* w1 = w0 + WP;
            const float* w2 = w1 + WP;
            const float* w3 = w2 + WP;
            const float* hb = s_h + bg * 4;
            const int kb = ksl * 128;
#pragma unroll 2
            for (int k = kb; k < kb + 128; k += 4) {
                float4 wv0 = *(const float4*)(w0 + k);
                float4 wv1 = *(const float4*)(w1 + k);
                float4 wv2 = *(const float4*)(w2 + k);
                float4 wv3 = *(const float4*)(w3 + k);
                float4 h0 = *(const float4*)(hb + (k + 0) * 64);
                float4 h1 = *(const float4*)(hb + (k + 1) * 64);
                float4 h2 = *(const float4*)(hb + (k + 2) * 64);
                float4 h3 = *(const float4*)(hb + (k + 3) * 64);
                FMASTEP(x, h0) FMASTEP(y, h1) FMASTEP(z, h2) FMASTEP(w, h3)
            }
            const int pb = ((ksl * 4 + rg) * 16 + bg) * 16;
            *(float4*)&s_p[pb + 0]  = a0;
            *(float4*)&s_p[pb + 4]  = a1;
            *(float4*)&s_p[pb + 8]  = a2;
            *(float4*)&s_p[pb + 12] = a3;
        }
        __syncthreads();

        // reduce k-slices + nonlinearity + cell update
        {
            const int rb = (bb >> 2) * 16 + ui * 4 + (bb & 3);
            float gi = xa0 + s_p[rb +   0] + s_p[rb +   0 + 1024] + s_p[rb +   0 + 2048] + s_p[rb +   0 + 3072];
            float gf = xa1 + s_p[rb + 256] + s_p[rb + 256 + 1024] + s_p[rb + 256 + 2048] + s_p[rb + 256 + 3072];
            float gg = xa2 + s_p[rb + 512] + s_p[rb + 512 + 1024] + s_p[rb + 512 + 2048] + s_p[rb + 512 + 3072];
            float go = xa3 + s_p[rb + 768] + s_p[rb + 768 + 1024] + s_p[rb + 768 + 2048] + s_p[rb + 768 + 3072];
            float iv = sigf(gi), fv = sigf(gf), gv = tanhf(gg), ov = sigf(go);
            c = fv * c + iv * gv;
            float hv = ov * tanhf(c);
            __stcg(&g_hbuf[(t + 1) & 1][u_glob * Bz + bb], hv);
            if (hs) hs[((size_t)t * Hz + u_glob) * Bz + bb] = hv;
        }
        __threadfence();
        __syncthreads();
        if (tid == 0) {
            atomicAdd(&g_barrier, 1u);
            unsigned tgt = (unsigned)(t + 1) * gridDim.x;
            while (*((volatile unsigned*)&g_barrier) < tgt) { __nanosleep(32); }
        }
        __syncthreads();
    }
}

// ------------------- mu / logvar / z (reads g_hbuf[0]) ---------------------
__global__ void k_latent(const float* __restrict__ muw, const float* __restrict__ mub,
                         const float* __restrict__ lvw, const float* __restrict__ lvb,
                         const float* __restrict__ eps, float* __restrict__ out) {
    int b = blockIdx.x, l = threadIdx.x;        // 64 blocks x 128 threads
    __shared__ float s_h[Hz];
    for (int k = l; k < Hz; k += 128) s_h[k] = g_hbuf[0][k * Bz + b];
    __syncthreads();
    float m = mub[l], v = lvb[l];
    for (int k = 0; k < Hz; ++k) {
        float h = s_h[k];
        m += muw[l * Hz + k] * h;
        v += lvw[l * Hz + k] * h;
    }
    out[512000 + b * LATz + l] = m;
    out[520192 + b * LATz + l] = v;
    g_z[b * LATz + l] = m + eps[b * LATz + l] * __expf(0.5f * v);
}

// --------------------------- d = z @ dec_in_wT + b -------------------------
__global__ void k_d(const float* __restrict__ w, const float* __restrict__ bias) {
    int b = blockIdx.x, h = threadIdx.x;        // 64 x 512
    __shared__ float s_z[LATz];
    if (h < LATz) s_z[h] = g_z[b * LATz + h];
    __syncthreads();
    float a = bias[h];
#pragma unroll 4
    for (int l = 0; l < LATz; ++l) a += w[h * LATz + l] * s_z[l];
    g_d[b * Hz + h] = a;
}

// ------------------- decoder gate preacts (constant over t) ----------------
__global__ void k_xgdec(const float* __restrict__ wih, const float* __restrict__ bih,
                        const float* __restrict__ bhh) {
    int b = blockIdx.x, gc = blockIdx.y;
    int g = gc * 512 + threadIdx.x;
    __shared__ float s_d[Hz];
    s_d[threadIdx.x] = g_d[b * Hz + threadIdx.x];
    __syncthreads();
    float a = bih[g] + bhh[g];
#pragma unroll 4
    for (int k = 0; k < Hz; ++k) a += wih[(size_t)g * Hz + k] * s_d[k];
    g_xgdec[g * Bz + b] = a;
}

// --------------------------- output projection -----------------------------
__global__ void __launch_bounds__(512) k_out(const float* __restrict__ w,
                                             const float* __restrict__ bias,
                                             float* __restrict__ out) {
    int t = blockIdx.x;
    __shared__ float s_w[8 * 520];
    __shared__ float s_h[64 * 64];
    int tid = threadIdx.x;
    for (int i = tid; i < INz * Hz; i += 512) s_w[(i >> 9) * 520 + (i & 511)] = w[i];
    int b = tid >> 3, o = tid & 7;
    float acc = bias[o];
    for (int kc = 0; kc < Hz; kc += 64) {
        __syncthreads();
        for (int i = tid; i < 1024; i += 512)
            *(float4*)&s_h[i * 4] = *(const float4*)&g_hs[((size_t)t * Hz + kc) * Bz + i * 4];
        __syncthreads();
#pragma unroll
        for (int kk = 0; kk < 64; ++kk) acc += s_h[kk * 64 + b] * s_w[o * 520 + kc + kk];
    }
    out[((size_t)b * Tz + t) * INz + o] = acc;
}

// ---------------------------------------------------------------------------
extern "C" void kernel_launch(void* const* d_in, const int* in_sizes, int n_in,
                              void* d_out, int out_size) {
    const float* x        = (const float*)d_in[0];
    const float* eps      = (const float*)d_in[1];
    const float* fcin_w   = (const float*)d_in[2];
    const float* fcin_b   = (const float*)d_in[3];
    const float* enc_wih  = (const float*)d_in[4];
    const float* enc_whh  = (const float*)d_in[5];
    const float* enc_bih  = (const float*)d_in[6];
    const float* enc_bhh  = (const float*)d_in[7];
    const float* mu_w     = (const float*)d_in[8];
    const float* mu_b     = (const float*)d_in[9];
    const float* lv_w     = (const float*)d_in[10];
    const float* lv_b     = (const float*)d_in[11];
    const float* din_w    = (const float*)d_in[12];
    const float* din_b    = (const float*)d_in[13];
    const float* dec_wih  = (const float*)d_in[14];
    const float* dec_whh  = (const float*)d_in[15];
    const float* dec_bih  = (const float*)d_in[16];
    const float* dec_bhh  = (const float*)d_in[17];
    const float* out_w    = (const float*)d_in[18];
    const float* out_b    = (const float*)d_in[19];
    float* out = (float*)d_out;

    cudaFuncSetAttribute(k_recur, cudaFuncAttributeMaxDynamicSharedMemorySize, SMEM_RECUR);

    k_ema<<<1, 64>>>(x);
    k_hin<<<dim3(Tz, Hz / 64), 256>>>(x, fcin_w, fcin_b);
    k_xg<<<dim3(Tz, Z4z / 128), 256>>>(enc_wih, enc_bih, enc_bhh);
    k_reset<<<129, 256>>>();
    k_recur<<<128, 256, SMEM_RECUR>>>(enc_whh, 0);
    k_latent<<<Bz, LATz>>>(mu_w, mu_b, lv_w, lv_b, eps, out);
    k_d<<<Bz, Hz>>>(din_w, din_b);
    k_xgdec<<<dim3(Bz, 4), 512>>>(dec_wih, dec_bih, dec_bhh);
    k_reset<<<129, 256>>>();
    k_recur<<<128, 256, SMEM_RECUR>>>(dec_whh, 1);
    k_out<<<Tz, 512>>>(out_w, out_b, out);
}

// round 11
// speedup vs baseline: 1.3639x; 1.3639x over previous
#include <cuda_runtime.h>
#include <cuda_bf16.h>

// ---------------------------------------------------------------------------
// LSTM-VAE forward.  B=64, T=1000, IN=8, H=512, Z4=2048, LAT=128
// tf32 tensor-core GEMMs (mma.sync.m16n8k8) for xg projection + recurrence.
// Output layout: [recon (B,T,IN) | mu (B,LAT) | logvar (B,LAT)]
// ---------------------------------------------------------------------------

#define Bz   64
#define Tz   1000
#define INz  8
#define Hz   512
#define Z4z  2048
#define LATz 128

// ------------------------- scratch (__device__ globals) --------------------
__device__ float g_e[Bz * Tz];                       // EMA channel      (B,T)
__device__ float g_hin[(size_t)Tz * Hz * Bz];        // enc input        (T,H,B)
__device__ float g_xg[(size_t)Tz * Z4z * Bz];        // enc gate preacts (T,Z4,B)
__device__ float g_xgdec[Z4z * Bz];                  // dec gate preacts (Z4,B)
__device__ float g_hbuf[2][Hz * Bz];                 // h double buffer  ([k][b])
__device__ float g_hs[(size_t)Tz * Hz * Bz];         // dec hidden seq   (T,H,B)
__device__ float g_z[Bz * LATz];
__device__ float g_d[Bz * Hz];
__device__ unsigned g_barrier;

__device__ __forceinline__ float sigf(float x) { return 1.f / (1.f + __expf(-x)); }

// tf32 helpers ---------------------------------------------------------------
__device__ __forceinline__ float tf32r(float f) {
    unsigned u;
    asm("cvt.rna.tf32.f32 %0, %1;" : "=r"(u) : "f"(f));
    return __uint_as_float(u);
}
__device__ __forceinline__ void mma8(float* d, const unsigned* a, unsigned b0, unsigned b1) {
    asm volatile(
        "mma.sync.aligned.m16n8k8.row.col.f32.tf32.tf32.f32 "
        "{%0,%1,%2,%3},{%4,%5,%6,%7},{%8,%9},{%0,%1,%2,%3};"
        : "+f"(d[0]), "+f"(d[1]), "+f"(d[2]), "+f"(d[3])
        : "r"(a[0]), "r"(a[1]), "r"(a[2]), "r"(a[3]), "r"(b0), "r"(b1));
}

// ------------------------------ EMA (parallel scan) -------------------------
// 512 threads: (b = tid&63, chunk c = tid>>6), chunks of 125.  0.9^125 carry.
__global__ void k_ema(const float* __restrict__ x) {
    __shared__ float s_end[8 * 64];
    __shared__ float s_init[8 * 64];
    int tid = threadIdx.x, b = tid & 63, c = tid >> 6;
    int t0 = c * 125;
    float e = 0.f;
    for (int i = 0; i < 125; ++i) {
        int t = t0 + i;
        float v = x[((size_t)b * Tz + t) * INz + 1];
        e = (c == 0 && i == 0) ? v : (0.1f * v + 0.9f * e);
        g_e[b * Tz + t] = e;
    }
    s_end[c * 64 + b] = e;
    __syncthreads();
    if (tid < 64) {
        const float P125 = 1.906849e-6f;       // 0.9^125
        float E = s_end[0 * 64 + tid];         // chunk0 is exact
        for (int cc = 1; cc < 8; ++cc) {
            s_init[cc * 64 + tid] = E;
            E = s_end[cc * 64 + tid] + E * P125;
        }
    }
    __syncthreads();
    if (c >= 1) {
        float I = s_init[c * 64 + b];
        float pw = 0.9f;
        for (int i = 0; i < 125; ++i) {
            g_e[b * Tz + t0 + i] += I * pw;
            pw *= 0.9f;
        }
    }
}

// ---------------- input FC + ReLU + positional encoding --------------------
__global__ void __launch_bounds__(256) k_hin(const float* __restrict__ x,
                                             const float* __restrict__ w,
                                             const float* __restrict__ bias) {
    int t = blockIdx.x, ht = blockIdx.y * 64;
    __shared__ float s_x[64][8];
    __shared__ float s_w[64][8];
    __shared__ float s_b[64];
    __shared__ float s_pe[64];
    int tid = threadIdx.x;

    for (int i = tid; i < 512; i += 256) {
        int bb = i >> 3, ii = i & 7;
        float v = x[((size_t)bb * Tz + t) * INz + ii];
        if (ii == 1) v = g_e[bb * Tz + t];
        s_x[bb][ii] = v;
    }
    for (int i = tid; i < 512; i += 256) {
        int hh = i >> 3, ii = i & 7;
        s_w[hh][ii] = w[(ht + hh) * INz + ii];
    }
    if (tid < 64) {
        int h = ht + tid;
        s_b[tid] = bias[h];
        int j = h >> 1;
        float div = __expf(-(float)(2 * j) * (9.2103403719761836f / 512.f));
        float ang = (float)t * div;
        s_pe[tid] = 0.1f * ((h & 1) ? cosf(ang) : sinf(ang));
    }
    __syncthreads();

    int hh = tid >> 2, bq = tid & 3;
    for (int q = 0; q < 16; ++q) {
        int bb = bq * 16 + q;
        float a = s_b[hh];
#pragma unroll
        for (int i = 0; i < 8; ++i) a += s_w[hh][i] * s_x[bb][i];
        a = fmaxf(a, 0.f) + s_pe[hh];
        g_hin[((size_t)t * Hz + ht + hh) * Bz + bb] = a;
    }
}

// ------------- encoder gate preactivations: xg = hin @ w_ihT + b -----------
// tf32 mma GEMM.  grid (Tz/2, 16): block = 128 gate rows x 64 batch x 2 t's.
// 8 warps = 4 row-groups(32) x 2 batch-halves(32).
#define XG_SW_PITCH 68
#define XG_SH_PITCH 72
#define SMEM_XG ((128 * XG_SW_PITCH + 2 * 64 * XG_SH_PITCH) * 4)

__global__ void __launch_bounds__(256) k_xg(const float* __restrict__ wih,
                                            const float* __restrict__ bih,
                                            const float* __restrict__ bhh) {
    extern __shared__ float sm[];
    float* s_w = sm;                               // [128][68]
    float* s_h = sm + 128 * XG_SW_PITCH;           // [2][64][72]

    const int t0 = blockIdx.x * 2, g0 = blockIdx.y * 128;
    const int tid = threadIdx.x;
    const int wid = tid >> 5, lane = tid & 31;
    const int mg = wid >> 1, bg = wid & 1;
    const int g = lane >> 2, tg = lane & 3;

    float acc[2][2][4][4];
#pragma unroll
    for (int a = 0; a < 2; ++a)
#pragma unroll
        for (int b = 0; b < 2; ++b)
#pragma unroll
            for (int c = 0; c < 4; ++c)
#pragma unroll
                for (int d = 0; d < 4; ++d) acc[a][b][c][d] = 0.f;

    for (int kc = 0; kc < Hz; kc += 64) {
        // stage w chunk [128 rows][64 k] = 2048 float4, tf32-rounded
#pragma unroll
        for (int i = 0; i < 8; ++i) {
            int idx = tid + i * 256;               // 0..2047
            int r = idx >> 4, k4 = idx & 15;
            float4 v = *(const float4*)&wih[(size_t)(g0 + r) * Hz + kc + k4 * 4];
            v.x = tf32r(v.x); v.y = tf32r(v.y); v.z = tf32r(v.z); v.w = tf32r(v.w);
            *(float4*)&s_w[r * XG_SW_PITCH + k4 * 4] = v;
        }
        // stage h chunks for both t's [64 k][64 b] x2 = 2048 float4
#pragma unroll
        for (int i = 0; i < 8; ++i) {
            int idx = tid + i * 256;               // 0..2047
            int t2 = idx >> 10, rem = idx & 1023;
            int kk = rem >> 4, b4 = rem & 15;
            float4 v = *(const float4*)&g_hin[((size_t)(t0 + t2) * Hz + kc + kk) * Bz + b4 * 4];
            v.x = tf32r(v.x); v.y = tf32r(v.y); v.z = tf32r(v.z); v.w = tf32r(v.w);
            *(float4*)&s_h[t2 * (64 * XG_SH_PITCH) + kk * XG_SH_PITCH + b4 * 4] = v;
        }
        __syncthreads();

#pragma unroll
        for (int kk = 0; kk < 8; ++kk) {
            unsigned A0[4], A1[4];
#pragma unroll
            for (int j = 0; j < 4; ++j) {
                int rowa = mg * 32 + ((j & 1) << 3) + g;
                int ka = kk * 8 + tg + ((j >> 1) << 2);
                A0[j] = __float_as_uint(s_w[rowa * XG_SW_PITCH + ka]);
                A1[j] = __float_as_uint(s_w[(rowa + 16) * XG_SW_PITCH + ka]);
            }
#pragma unroll
            for (int t2 = 0; t2 < 2; ++t2)
#pragma unroll
                for (int nt = 0; nt < 4; ++nt) {
                    int n = bg * 32 + nt * 8 + g;
                    const float* hb = s_h + t2 * (64 * XG_SH_PITCH);
                    unsigned b0 = __float_as_uint(hb[(kk * 8 + tg) * XG_SH_PITCH + n]);
                    unsigned b1 = __float_as_uint(hb[(kk * 8 + tg + 4) * XG_SH_PITCH + n]);
                    mma8(acc[t2][0][nt], A0, b0, b1);
                    mma8(acc[t2][1][nt], A1, b0, b1);
                }
        }
        __syncthreads();
    }

    // epilogue: + bias, store
#pragma unroll
    for (int mt = 0; mt < 2; ++mt) {
        int row = g0 + mg * 32 + mt * 16 + g;
        float bs0 = bih[row] + bhh[row];
        float bs1 = bih[row + 8] + bhh[row + 8];
#pragma unroll
        for (int t2 = 0; t2 < 2; ++t2)
#pragma unroll
            for (int nt = 0; nt < 4; ++nt) {
                int col = bg * 32 + nt * 8 + 2 * tg;
                size_t base = ((size_t)(t0 + t2) * Z4z + row) * Bz + col;
                float2 v0 = make_float2(acc[t2][mt][nt][0] + bs0, acc[t2][mt][nt][1] + bs0);
                *(float2*)&g_xg[base] = v0;
                float2 v1 = make_float2(acc[t2][mt][nt][2] + bs1, acc[t2][mt][nt][3] + bs1);
                *(float2*)&g_xg[base + (size_t)8 * Bz] = v1;
            }
    }
}

// --------------------------- reset barrier + h ------------------------------
__global__ void k_reset() {
    int i = blockIdx.x * blockDim.x + threadIdx.x;
    if (i == 0) g_barrier = 0u;
    if (i < Hz * Bz) { g_hbuf[0][i] = 0.f; g_hbuf[1][i] = 0.f; }
}

// --------------------------- persistent LSTM recurrence ---------------------
// 64 blocks x 256 threads.  Block owns 8 units (32 gate rows) x 64 batch.
// 8 warps = 8 K-slices of 64; stationary w_hh fragments preloaded in regs.
#define RC_SH_PITCH 72
#define RC_SP_PITCH 65
#define RC_SH_FLTS  (Hz * RC_SH_PITCH)              // 36864
#define RC_SP_FLTS  (8 * 32 * RC_SP_PITCH)          // 16640
#define SMEM_RECUR  ((RC_SH_FLTS + RC_SP_FLTS) * 4) // 214016

__global__ void __launch_bounds__(256, 1) k_recur(const float* __restrict__ whh,
                                                  int phase) {
    const float* xg = phase ? g_xgdec : g_xg;
    const size_t tstr = phase ? 0 : (size_t)Z4z * Bz;
    float* hs = phase ? g_hs : (float*)0;

    extern __shared__ float sm[];
    float* s_h = sm;                    // [512][72]
    float* s_p = sm + RC_SH_FLTS;       // [8 ks][32 r][65]

    const int tid = threadIdx.x, bid = blockIdx.x;
    const int ks = tid >> 5, lane = tid & 31;
    const int g = lane >> 2, tg = lane & 3;

    // preload stationary A fragments (w_hh slice, tf32)
    // local row r = gate*8 + ui -> global gate row = gate*512 + bid*8 + ui
    unsigned Af[2][8][4];
#pragma unroll
    for (int mt = 0; mt < 2; ++mt)
#pragma unroll
        for (int kk = 0; kk < 8; ++kk)
#pragma unroll
            for (int j = 0; j < 4; ++j) {
                int r = mt * 16 + ((j & 1) << 3) + g;
                int k = ks * 64 + kk * 8 + tg + ((j >> 1) << 2);
                int gate = r >> 3, ui = r & 7;
                int grow = gate * Hz + bid * 8 + ui;
                Af[mt][kk][j] = __float_as_uint(tf32r(whh[(size_t)grow * Hz + k]));
            }

    // cell-update mapping: 2 cells/thread
    float c0 = 0.f, c1 = 0.f;
    const int ui0 = tid >> 6,         bb0 = tid & 63;
    const int ui1 = (tid + 256) >> 6, bb1 = tid & 63;
    __syncthreads();

    for (int t = 0; t < Tz; ++t) {
        // prefetch gate preactivations (8 per thread)
        const float* xp = xg + (size_t)t * tstr;
        float xa0[4], xa1[4];
#pragma unroll
        for (int gt = 0; gt < 4; ++gt) {
            xa0[gt] = __ldg(&xp[(gt * Hz + bid * 8 + ui0) * Bz + bb0]);
            xa1[gt] = __ldg(&xp[(gt * Hz + bid * 8 + ui1) * Bz + bb1]);
        }

        // stage h_{t-1} (L2 -> SMEM): 8192 float4 = Hz*Bz floats, tf32-rounded
        {
            const float4* src = (const float4*)g_hbuf[t & 1];
#pragma unroll
            for (int i = 0; i < 32; ++i) {
                int idx = tid + (i << 8);          // 0..8191
                int k = idx >> 4, b4 = idx & 15;
                float4 v = __ldcg(&src[idx]);
                v.x = tf32r(v.x); v.y = tf32r(v.y); v.z = tf32r(v.z); v.w = tf32r(v.w);
                *(float4*)&s_h[k * RC_SH_PITCH + b4 * 4] = v;
            }
        }
        __syncthreads();

        // mma: 2 m-tiles x 8 n-tiles x 8 k-steps over this warp's K-slice
        float acc[2][8][4];
#pragma unroll
        for (int a = 0; a < 2; ++a)
#pragma unroll
            for (int b = 0; b < 8; ++b)
#pragma unroll
                for (int c = 0; c < 4; ++c) acc[a][b][c] = 0.f;

#pragma unroll
        for (int nt = 0; nt < 8; ++nt)
#pragma unroll
            for (int kk = 0; kk < 8; ++kk) {
                int kr = ks * 64 + kk * 8;
                unsigned b0 = __float_as_uint(s_h[(kr + tg) * RC_SH_PITCH + nt * 8 + g]);
                unsigned b1 = __float_as_uint(s_h[(kr + tg + 4) * RC_SH_PITCH + nt * 8 + g]);
                mma8(acc[0][nt], Af[0][kk], b0, b1);
                mma8(acc[1][nt], Af[1][kk], b0, b1);
            }

        // store partials
#pragma unroll
        for (int mt = 0; mt < 2; ++mt)
#pragma unroll
            for (int nt = 0; nt < 8; ++nt) {
                int r = mt * 16 + g, b = nt * 8 + 2 * tg;
                float* p = s_p + ks * (32 * RC_SP_PITCH) + r * RC_SP_PITCH + b;
                p[0] = acc[mt][nt][0];
                p[1] = acc[mt][nt][1];
                p[8 * RC_SP_PITCH]     = acc[mt][nt][2];
                p[8 * RC_SP_PITCH + 1] = acc[mt][nt][3];
            }
        __syncthreads();

        // reduce K-slices + nonlinearity + cell update (2 cells/thread)
        {
            float gs[4];
#pragma unroll
            for (int gt = 0; gt < 4; ++gt) {
                int r = gt * 8 + ui0;
                float s = xa0[gt];
#pragma unroll
                for (int k2 = 0; k2 < 8; ++k2)
                    s += s_p[k2 * (32 * RC_SP_PITCH) + r * RC_SP_PITCH + bb0];
                gs[gt] = s;
            }
            float iv = sigf(gs[0]), fv = sigf(gs[1]), gv = tanhf(gs[2]), ov = sigf(gs[3]);
            c0 = fv * c0 + iv * gv;
            float hv = ov * tanhf(c0);
            int u = bid * 8 + ui0;
            __stcg(&g_hbuf[(t + 1) & 1][u * Bz + bb0], hv);
            if (hs) hs[((size_t)t * Hz + u) * Bz + bb0] = hv;
        }
        {
            float gs[4];
#pragma unroll
            for (int gt = 0; gt < 4; ++gt) {
                int r = gt * 8 + ui1;
                float s = xa1[gt];
#pragma unroll
                for (int k2 = 0; k2 < 8; ++k2)
                    s += s_p[k2 * (32 * RC_SP_PITCH) + r * RC_SP_PITCH + bb1];
                gs[gt] = s;
            }
            float iv = sigf(gs[0]), fv = sigf(gs[1]), gv = tanhf(gs[2]), ov = sigf(gs[3]);
            c1 = fv * c1 + iv * gv;
            float hv = ov * tanhf(c1);
            int u = bid * 8 + ui1;
            __stcg(&g_hbuf[(t + 1) & 1][u * Bz + bb1], hv);
            if (hs) hs[((size_t)t * Hz + u) * Bz + bb1] = hv;
        }
        __threadfence();
        __syncthreads();
        if (tid == 0) {
            atomicAdd(&g_barrier, 1u);
            unsigned tgt = (unsigned)(t + 1) * gridDim.x;
            while (*((volatile unsigned*)&g_barrier) < tgt) { __nanosleep(32); }
        }
        __syncthreads();
    }
}

// ------------------- mu / logvar / z (reads g_hbuf[0]) ---------------------
__global__ void k_latent(const float* __restrict__ muw, const float* __restrict__ mub,
                         const float* __restrict__ lvw, const float* __restrict__ lvb,
                         const float* __restrict__ eps, float* __restrict__ out) {
    int b = blockIdx.x, l = threadIdx.x;        // 64 blocks x 128 threads
    __shared__ float s_h[Hz];
    for (int k = l; k < Hz; k += 128) s_h[k] = g_hbuf[0][k * Bz + b];
    __syncthreads();
    float m = mub[l], v = lvb[l];
    for (int k = 0; k < Hz; ++k) {
        float h = s_h[k];
        m += muw[l * Hz + k] * h;
        v += lvw[l * Hz + k] * h;
    }
    out[512000 + b * LATz + l] = m;
    out[520192 + b * LATz + l] = v;
    g_z[b * LATz + l] = m + eps[b * LATz + l] * __expf(0.5f * v);
}

// --------------------------- d = z @ dec_in_wT + b -------------------------
__global__ void k_d(const float* __restrict__ w, const float* __restrict__ bias) {
    int b = blockIdx.x, h = threadIdx.x;        // 64 x 512
    __shared__ float s_z[LATz];
    if (h < LATz) s_z[h] = g_z[b * LATz + h];
    __syncthreads();
    float a = bias[h];
#pragma unroll 4
    for (int l = 0; l < LATz; ++l) a += w[h * LATz + l] * s_z[l];
    g_d[b * Hz + h] = a;
}

// ------------------- decoder gate preacts (constant over t) ----------------
__global__ void k_xgdec(const float* __restrict__ wih, const float* __restrict__ bih,
                        const float* __restrict__ bhh) {
    int b = blockIdx.x, gc = blockIdx.y;
    int g = gc * 512 + threadIdx.x;
    __shared__ float s_d[Hz];
    s_d[threadIdx.x] = g_d[b * Hz + threadIdx.x];
    __syncthreads();
    float a = bih[g] + bhh[g];
#pragma unroll 4
    for (int k = 0; k < Hz; ++k) a += wih[(size_t)g * Hz + k] * s_d[k];
    g_xgdec[g * Bz + b] = a;
}

// --------------------------- output projection -----------------------------
__global__ void __launch_bounds__(512) k_out(const float* __restrict__ w,
                                             const float* __restrict__ bias,
                                             float* __restrict__ out) {
    int t = blockIdx.x;
    __shared__ float s_w[8 * 520];
    __shared__ float s_h[64 * 64];
    int tid = threadIdx.x;
    for (int i = tid; i < INz * Hz; i += 512) s_w[(i >> 9) * 520 + (i & 511)] = w[i];
    int b = tid >> 3, o = tid & 7;
    float acc = bias[o];
    for (int kc = 0; kc < Hz; kc += 64) {
        __syncthreads();
        for (int i = tid; i < 1024; i += 512)
            *(float4*)&s_h[i * 4] = *(const float4*)&g_hs[((size_t)t * Hz + kc) * Bz + i * 4];
        __syncthreads();
#pragma unroll
        for (int kk = 0; kk < 64; ++kk) acc += s_h[kk * 64 + b] * s_w[o * 520 + kc + kk];
    }
    out[((size_t)b * Tz + t) * INz + o] = acc;
}

// ---------------------------------------------------------------------------
extern "C" void kernel_launch(void* const* d_in, const int* in_sizes, int n_in,
                              void* d_out, int out_size) {
    const float* x        = (const float*)d_in[0];
    const float* eps      = (const float*)d_in[1];
    const float* fcin_w   = (const float*)d_in[2];
    const float* fcin_b   = (const float*)d_in[3];
    const float* enc_wih  = (const float*)d_in[4];
    const float* enc_whh  = (const float*)d_in[5];
    const float* enc_bih  = (const float*)d_in[6];
    const float* enc_bhh  = (const float*)d_in[7];
    const float* mu_w     = (const float*)d_in[8];
    const float* mu_b     = (const float*)d_in[9];
    const float* lv_w     = (const float*)d_in[10];
    const float* lv_b     = (const float*)d_in[11];
    const float* din_w    = (const float*)d_in[12];
    const float* din_b    = (const float*)d_in[13];
    const float* dec_wih  = (const float*)d_in[14];
    const float* dec_whh  = (const float*)d_in[15];
    const float* dec_bih  = (const float*)d_in[16];
    const float* dec_bhh  = (const float*)d_in[17];
    const float* out_w    = (const float*)d_in[18];
    const float* out_b    = (const float*)d_in[19];
    float* out = (float*)d_out;

    cudaFuncSetAttribute(k_recur, cudaFuncAttributeMaxDynamicSharedMemorySize, SMEM_RECUR);
    cudaFuncSetAttribute(k_xg, cudaFuncAttributeMaxDynamicSharedMemorySize, SMEM_XG);

    k_ema<<<1, 512>>>(x);
    k_hin<<<dim3(Tz, Hz / 64), 256>>>(x, fcin_w, fcin_b);
    k_xg<<<dim3(Tz / 2, Z4z / 128), 256, SMEM_XG>>>(enc_wih, enc_bih, enc_bhh);
    k_reset<<<129, 256>>>();
    k_recur<<<64, 256, SMEM_RECUR>>>(enc_whh, 0);
    k_latent<<<Bz, LATz>>>(mu_w, mu_b, lv_w, lv_b, eps, out);
    k_d<<<Bz, Hz>>>(din_w, din_b);
    k_xgdec<<<dim3(Bz, 4), 512>>>(dec_wih, dec_bih, dec_bhh);
    k_reset<<<129, 256>>>();
    k_recur<<<64, 256, SMEM_RECUR>>>(dec_whh, 1);
    k_out<<<Tz, 512>>>(out_w, out_b, out);
}

// round 12
// speedup vs baseline: 1.5596x; 1.1435x over previous
#include <cuda_runtime.h>
#include <cuda_bf16.h>

// ---------------------------------------------------------------------------
// LSTM-VAE forward.  B=64, T=1000, IN=8, H=512, Z4=2048, LAT=128
// tf32 tensor-core GEMMs (mma.sync.m16n8k8) for xg projection + recurrence.
// Output layout: [recon (B,T,IN) | mu (B,LAT) | logvar (B,LAT)]
// ---------------------------------------------------------------------------

#define Bz   64
#define Tz   1000
#define INz  8
#define Hz   512
#define Z4z  2048
#define LATz 128

// ------------------------- scratch (__device__ globals) --------------------
__device__ float g_e[Bz * Tz];                       // EMA channel      (B,T)
__device__ float g_hin[(size_t)Tz * Hz * Bz];        // enc input        (T,H,B)
__device__ float g_xg[(size_t)Tz * Z4z * Bz];        // enc gate preacts (T,Z4,B)
__device__ float g_xgdec[Z4z * Bz];                  // dec gate preacts (Z4,B)
__device__ float g_hbuf[2][Hz * Bz];                 // h double buffer  ([k][b])
__device__ float g_hs[(size_t)Tz * Hz * Bz];         // dec hidden seq   (T,H,B)
__device__ float g_z[Bz * LATz];
__device__ float g_d[Bz * Hz];
__device__ unsigned g_barrier;

__device__ __forceinline__ float sigf(float x) { return 1.f / (1.f + __expf(-x)); }

// tf32 helpers ---------------------------------------------------------------
__device__ __forceinline__ float tf32r(float f) {
    unsigned u;
    asm("cvt.rna.tf32.f32 %0, %1;" : "=r"(u) : "f"(f));
    return __uint_as_float(u);
}
__device__ __forceinline__ void mma8(float* d, const unsigned* a, unsigned b0, unsigned b1) {
    asm volatile(
        "mma.sync.aligned.m16n8k8.row.col.f32.tf32.tf32.f32 "
        "{%0,%1,%2,%3},{%4,%5,%6,%7},{%8,%9},{%0,%1,%2,%3};"
        : "+f"(d[0]), "+f"(d[1]), "+f"(d[2]), "+f"(d[3])
        : "r"(a[0]), "r"(a[1]), "r"(a[2]), "r"(a[3]), "r"(b0), "r"(b1));
}

// ---------------------- EMA (parallel scan) + reset ------------------------
// Also resets g_hbuf / g_barrier so k_recur(enc) is launch #4 (ncu capture).
__global__ void k_ema(const float* __restrict__ x) {
    __shared__ float s_end[8 * 64];
    __shared__ float s_init[8 * 64];
    int tid = threadIdx.x, b = tid & 63, c = tid >> 6;

    // fused reset
    for (int i = tid; i < Hz * Bz; i += 512) { g_hbuf[0][i] = 0.f; g_hbuf[1][i] = 0.f; }
    if (tid == 0) g_barrier = 0u;

    int t0 = c * 125;
    float e = 0.f;
    for (int i = 0; i < 125; ++i) {
        int t = t0 + i;
        float v = x[((size_t)b * Tz + t) * INz + 1];
        e = (c == 0 && i == 0) ? v : (0.1f * v + 0.9f * e);
        g_e[b * Tz + t] = e;
    }
    s_end[c * 64 + b] = e;
    __syncthreads();
    if (tid < 64) {
        const float P125 = 1.906849e-6f;       // 0.9^125
        float E = s_end[0 * 64 + tid];         // chunk0 is exact
        for (int cc = 1; cc < 8; ++cc) {
            s_init[cc * 64 + tid] = E;
            E = s_end[cc * 64 + tid] + E * P125;
        }
    }
    __syncthreads();
    if (c >= 1) {
        float I = s_init[c * 64 + b];
        float pw = 0.9f;
        for (int i = 0; i < 125; ++i) {
            g_e[b * Tz + t0 + i] += I * pw;
            pw *= 0.9f;
        }
    }
}

// ---------------- input FC + ReLU + positional encoding --------------------
__global__ void __launch_bounds__(256) k_hin(const float* __restrict__ x,
                                             const float* __restrict__ w,
                                             const float* __restrict__ bias) {
    int t = blockIdx.x, ht = blockIdx.y * 64;
    __shared__ float s_x[64][8];
    __shared__ float s_w[64][8];
    __shared__ float s_b[64];
    __shared__ float s_pe[64];
    int tid = threadIdx.x;

    for (int i = tid; i < 512; i += 256) {
        int bb = i >> 3, ii = i & 7;
        float v = x[((size_t)bb * Tz + t) * INz + ii];
        if (ii == 1) v = g_e[bb * Tz + t];
        s_x[bb][ii] = v;
    }
    for (int i = tid; i < 512; i += 256) {
        int hh = i >> 3, ii = i & 7;
        s_w[hh][ii] = w[(ht + hh) * INz + ii];
    }
    if (tid < 64) {
        int h = ht + tid;
        s_b[tid] = bias[h];
        int j = h >> 1;
        float div = __expf(-(float)(2 * j) * (9.2103403719761836f / 512.f));
        float ang = (float)t * div;
        s_pe[tid] = 0.1f * ((h & 1) ? cosf(ang) : sinf(ang));
    }
    __syncthreads();

    int hh = tid >> 2, bq = tid & 3;
    for (int q = 0; q < 16; ++q) {
        int bb = bq * 16 + q;
        float a = s_b[hh];
#pragma unroll
        for (int i = 0; i < 8; ++i) a += s_w[hh][i] * s_x[bb][i];
        a = fmaxf(a, 0.f) + s_pe[hh];
        g_hin[((size_t)t * Hz + ht + hh) * Bz + bb] = a;
    }
}

// ------------- encoder gate preactivations: xg = hin @ w_ihT + b -----------
// tf32 mma GEMM.  grid (Tz/2, 16): block = 128 gate rows x 64 batch x 2 t's.
#define XG_SW_PITCH 68
#define XG_SH_PITCH 72
#define SMEM_XG ((128 * XG_SW_PITCH + 2 * 64 * XG_SH_PITCH) * 4)

__global__ void __launch_bounds__(256) k_xg(const float* __restrict__ wih,
                                            const float* __restrict__ bih,
                                            const float* __restrict__ bhh) {
    extern __shared__ float sm[];
    float* s_w = sm;                               // [128][68]
    float* s_h = sm + 128 * XG_SW_PITCH;           // [2][64][72]

    const int t0 = blockIdx.x * 2, g0 = blockIdx.y * 128;
    const int tid = threadIdx.x;
    const int wid = tid >> 5, lane = tid & 31;
    const int mg = wid >> 1, bg = wid & 1;
    const int g = lane >> 2, tg = lane & 3;

    float acc[2][2][4][4];
#pragma unroll
    for (int a = 0; a < 2; ++a)
#pragma unroll
        for (int b = 0; b < 2; ++b)
#pragma unroll
            for (int c = 0; c < 4; ++c)
#pragma unroll
                for (int d = 0; d < 4; ++d) acc[a][b][c][d] = 0.f;

    for (int kc = 0; kc < Hz; kc += 64) {
        // stage w chunk [128 rows][64 k] = 2048 float4, tf32-rounded
#pragma unroll
        for (int i = 0; i < 8; ++i) {
            int idx = tid + i * 256;               // 0..2047
            int r = idx >> 4, k4 = idx & 15;
            float4 v = *(const float4*)&wih[(size_t)(g0 + r) * Hz + kc + k4 * 4];
            v.x = tf32r(v.x); v.y = tf32r(v.y); v.z = tf32r(v.z); v.w = tf32r(v.w);
            *(float4*)&s_w[r * XG_SW_PITCH + k4 * 4] = v;
        }
        // stage h chunks for both t's [64 k][64 b] x2 = 2048 float4
#pragma unroll
        for (int i = 0; i < 8; ++i) {
            int idx = tid + i * 256;               // 0..2047
            int t2 = idx >> 10, rem = idx & 1023;
            int kk = rem >> 4, b4 = rem & 15;
            float4 v = *(const float4*)&g_hin[((size_t)(t0 + t2) * Hz + kc + kk) * Bz + b4 * 4];
            v.x = tf32r(v.x); v.y = tf32r(v.y); v.z = tf32r(v.z); v.w = tf32r(v.w);
            *(float4*)&s_h[t2 * (64 * XG_SH_PITCH) + kk * XG_SH_PITCH + b4 * 4] = v;
        }
        __syncthreads();

#pragma unroll
        for (int kk = 0; kk < 8; ++kk) {
            unsigned A0[4], A1[4];
#pragma unroll
            for (int j = 0; j < 4; ++j) {
                int rowa = mg * 32 + ((j & 1) << 3) + g;
                int ka = kk * 8 + tg + ((j >> 1) << 2);
                A0[j] = __float_as_uint(s_w[rowa * XG_SW_PITCH + ka]);
                A1[j] = __float_as_uint(s_w[(rowa + 16) * XG_SW_PITCH + ka]);
            }
#pragma unroll
            for (int t2 = 0; t2 < 2; ++t2)
#pragma unroll
                for (int nt = 0; nt < 4; ++nt) {
                    int n = bg * 32 + nt * 8 + g;
                    const float* hb = s_h + t2 * (64 * XG_SH_PITCH);
                    unsigned b0 = __float_as_uint(hb[(kk * 8 + tg) * XG_SH_PITCH + n]);
                    unsigned b1 = __float_as_uint(hb[(kk * 8 + tg + 4) * XG_SH_PITCH + n]);
                    mma8(acc[t2][0][nt], A0, b0, b1);
                    mma8(acc[t2][1][nt], A1, b0, b1);
                }
        }
        __syncthreads();
    }

    // epilogue: + bias, store
#pragma unroll
    for (int mt = 0; mt < 2; ++mt) {
        int row = g0 + mg * 32 + mt * 16 + g;
        float bs0 = bih[row] + bhh[row];
        float bs1 = bih[row + 8] + bhh[row + 8];
#pragma unroll
        for (int t2 = 0; t2 < 2; ++t2)
#pragma unroll
            for (int nt = 0; nt < 4; ++nt) {
                int col = bg * 32 + nt * 8 + 2 * tg;
                size_t base = ((size_t)(t0 + t2) * Z4z + row) * Bz + col;
                float2 v0 = make_float2(acc[t2][mt][nt][0] + bs0, acc[t2][mt][nt][1] + bs0);
                *(float2*)&g_xg[base] = v0;
                float2 v1 = make_float2(acc[t2][mt][nt][2] + bs1, acc[t2][mt][nt][3] + bs1);
                *(float2*)&g_xg[base + (size_t)8 * Bz] = v1;
            }
    }
}

// --------------------------- reset barrier + h ------------------------------
__global__ void k_reset() {
    int i = blockIdx.x * blockDim.x + threadIdx.x;
    if (i == 0) g_barrier = 0u;
    if (i < Hz * Bz) { g_hbuf[0][i] = 0.f; g_hbuf[1][i] = 0.f; }
}

// --------------------------- persistent LSTM recurrence ---------------------
// 64 blocks x 256 threads.  Block owns 8 units (32 gate rows) x 64 batch.
// 8 warps = 8 K-slices of 64; stationary w_hh fragments preloaded in regs.
#define RC_SH_PITCH 72
#define RC_SP_PITCH 72                              // even: float2 epilogue
#define RC_SH_FLTS  (Hz * RC_SH_PITCH)              // 36864
#define RC_SP_FLTS  (8 * 32 * RC_SP_PITCH)          // 18432
#define SMEM_RECUR  ((RC_SH_FLTS + RC_SP_FLTS) * 4) // 221184

__global__ void __launch_bounds__(256, 1) k_recur(const float* __restrict__ whh,
                                                  int phase) {
    const float* xg = phase ? g_xgdec : g_xg;
    const size_t tstr = phase ? 0 : (size_t)Z4z * Bz;
    float* hs = phase ? g_hs : (float*)0;

    extern __shared__ float sm[];
    float* s_h = sm;                    // [512][72]
    float* s_p = sm + RC_SH_FLTS;       // [8 ks][32 r][72]

    const int tid = threadIdx.x, bid = blockIdx.x;
    const int ks = tid >> 5, lane = tid & 31;
    const int g = lane >> 2, tg = lane & 3;

    // preload stationary A fragments (w_hh slice, tf32-rounded once)
    // local row r = gate*8 + ui -> global gate row = gate*512 + bid*8 + ui
    unsigned Af[2][8][4];
#pragma unroll
    for (int mt = 0; mt < 2; ++mt)
#pragma unroll
        for (int kk = 0; kk < 8; ++kk)
#pragma unroll
            for (int j = 0; j < 4; ++j) {
                int r = mt * 16 + ((j & 1) << 3) + g;
                int k = ks * 64 + kk * 8 + tg + ((j >> 1) << 2);
                int gate = r >> 3, ui = r & 7;
                int grow = gate * Hz + bid * 8 + ui;
                Af[mt][kk][j] = __float_as_uint(tf32r(whh[(size_t)grow * Hz + k]));
            }

    // cell-update mapping: warp = unit, lane = 2 consecutive batch
    const int ui = tid >> 5, b2 = (tid & 31) * 2;
    const int u_glob = bid * 8 + ui;
    float c0 = 0.f, c1 = 0.f;
    __syncthreads();

    for (int t = 0; t < Tz; ++t) {
        // prefetch gate preactivations (4 float2 per thread, coalesced)
        const float* xp = xg + (size_t)t * tstr;
        float2 xa[4];
#pragma unroll
        for (int gt = 0; gt < 4; ++gt)
            xa[gt] = __ldg((const float2*)&xp[(gt * Hz + u_glob) * Bz + b2]);

        // stage h_{t-1} (L2 -> SMEM): 8192 float4; raw fp32 (HW truncates to tf32)
        {
            const float4* src = (const float4*)g_hbuf[t & 1];
#pragma unroll
            for (int i = 0; i < 32; ++i) {
                int idx = tid + (i << 8);          // 0..8191
                int k = idx >> 4, b4 = idx & 15;
                *(float4*)&s_h[k * RC_SH_PITCH + b4 * 4] = __ldcg(&src[idx]);
            }
        }
        __syncthreads();

        // mma: 2 m-tiles x 8 n-tiles x 8 k-steps over this warp's K-slice
        float acc[2][8][4];
#pragma unroll
        for (int a = 0; a < 2; ++a)
#pragma unroll
            for (int b = 0; b < 8; ++b)
#pragma unroll
                for (int c = 0; c < 4; ++c) acc[a][b][c] = 0.f;

#pragma unroll
        for (int nt = 0; nt < 8; ++nt)
#pragma unroll
            for (int kk = 0; kk < 8; ++kk) {
                int kr = ks * 64 + kk * 8;
                unsigned b0 = __float_as_uint(s_h[(kr + tg) * RC_SH_PITCH + nt * 8 + g]);
                unsigned b1 = __float_as_uint(s_h[(kr + tg + 4) * RC_SH_PITCH + nt * 8 + g]);
                mma8(acc[0][nt], Af[0][kk], b0, b1);
                mma8(acc[1][nt], Af[1][kk], b0, b1);
            }

        // store partials (float2)
#pragma unroll
        for (int mt = 0; mt < 2; ++mt)
#pragma unroll
            for (int nt = 0; nt < 8; ++nt) {
                int r = mt * 16 + g, b = nt * 8 + 2 * tg;
                float* p = s_p + ks * (32 * RC_SP_PITCH) + r * RC_SP_PITCH + b;
                *(float2*)&p[0] = make_float2(acc[mt][nt][0], acc[mt][nt][1]);
                *(float2*)&p[8 * RC_SP_PITCH] = make_float2(acc[mt][nt][2], acc[mt][nt][3]);
            }
        __syncthreads();

        // reduce K-slices + nonlinearity + cell update (2 consecutive batch)
        {
            float2 gs[4];
#pragma unroll
            for (int gt = 0; gt < 4; ++gt) {
                int r = gt * 8 + ui;
                float2 s = xa[gt];
#pragma unroll
                for (int k2 = 0; k2 < 8; ++k2) {
                    float2 v = *(const float2*)&s_p[k2 * (32 * RC_SP_PITCH) + r * RC_SP_PITCH + b2];
                    s.x += v.x; s.y += v.y;
                }
                gs[gt] = s;
            }
            float ivx = sigf(gs[0].x), fvx = sigf(gs[1].x), gvx = tanhf(gs[2].x), ovx = sigf(gs[3].x);
            float ivy = sigf(gs[0].y), fvy = sigf(gs[1].y), gvy = tanhf(gs[2].y), ovy = sigf(gs[3].y);
            c0 = fvx * c0 + ivx * gvx;
            c1 = fvy * c1 + ivy * gvy;
            float2 hv = make_float2(ovx * tanhf(c0), ovy * tanhf(c1));
            __stcg((float2*)&g_hbuf[(t + 1) & 1][u_glob * Bz + b2], hv);
            if (hs) *(float2*)&hs[((size_t)t * Hz + u_glob) * Bz + b2] = hv;
        }

        // grid barrier: single-thread fence + arrive + tight poll
        __syncthreads();
        if (tid == 0) {
            __threadfence();
            atomicAdd(&g_barrier, 1u);
            unsigned tgt = (unsigned)(t + 1) * gridDim.x;
            while (*((volatile unsigned*)&g_barrier) < tgt) {}
            __threadfence();
        }
        __syncthreads();
    }
}

// ------------------- mu / logvar / z (reads g_hbuf[0]) ---------------------
__global__ void k_latent(const float* __restrict__ muw, const float* __restrict__ mub,
                         const float* __restrict__ lvw, const float* __restrict__ lvb,
                         const float* __restrict__ eps, float* __restrict__ out) {
    int b = blockIdx.x, l = threadIdx.x;        // 64 blocks x 128 threads
    __shared__ float s_h[Hz];
    for (int k = l; k < Hz; k += 128) s_h[k] = g_hbuf[0][k * Bz + b];
    __syncthreads();
    float m = mub[l], v = lvb[l];
    for (int k = 0; k < Hz; ++k) {
        float h = s_h[k];
        m += muw[l * Hz + k] * h;
        v += lvw[l * Hz + k] * h;
    }
    out[512000 + b * LATz + l] = m;
    out[520192 + b * LATz + l] = v;
    g_z[b * LATz + l] = m + eps[b * LATz + l] * __expf(0.5f * v);
}

// --------------------------- d = z @ dec_in_wT + b -------------------------
__global__ void k_d(const float* __restrict__ w, const float* __restrict__ bias) {
    int b = blockIdx.x, h = threadIdx.x;        // 64 x 512
    __shared__ float s_z[LATz];
    if (h < LATz) s_z[h] = g_z[b * LATz + h];
    __syncthreads();
    float a = bias[h];
#pragma unroll 4
    for (int l = 0; l < LATz; ++l) a += w[h * LATz + l] * s_z[l];
    g_d[b * Hz + h] = a;
}

// ------------------- decoder gate preacts (constant over t) ----------------
__global__ void k_xgdec(const float* __restrict__ wih, const float* __restrict__ bih,
                        const float* __restrict__ bhh) {
    int b = blockIdx.x, gc = blockIdx.y;
    int g = gc * 512 + threadIdx.x;
    __shared__ float s_d[Hz];
    s_d[threadIdx.x] = g_d[b * Hz + threadIdx.x];
    __syncthreads();
    float a = bih[g] + bhh[g];
#pragma unroll 4
    for (int k = 0; k < Hz; ++k) a += wih[(size_t)g * Hz + k] * s_d[k];
    g_xgdec[g * Bz + b] = a;
}

// --------------------------- output projection -----------------------------
__global__ void __launch_bounds__(512) k_out(const float* __restrict__ w,
                                             const float* __restrict__ bias,
                                             float* __restrict__ out) {
    int t = blockIdx.x;
    __shared__ float s_w[8 * 520];
    __shared__ float s_h[64 * 64];
    int tid = threadIdx.x;
    for (int i = tid; i < INz * Hz; i += 512) s_w[(i >> 9) * 520 + (i & 511)] = w[i];
    int b = tid >> 3, o = tid & 7;
    float acc = bias[o];
    for (int kc = 0; kc < Hz; kc += 64) {
        __syncthreads();
        for (int i = tid; i < 1024; i += 512)
            *(float4*)&s_h[i * 4] = *(const float4*)&g_hs[((size_t)t * Hz + kc) * Bz + i * 4];
        __syncthreads();
#pragma unroll
        for (int kk = 0; kk < 64; ++kk) acc += s_h[kk * 64 + b] * s_w[o * 520 + kc + kk];
    }
    out[((size_t)b * Tz + t) * INz + o] = acc;
}

// ---------------------------------------------------------------------------
extern "C" void kernel_launch(void* const* d_in, const int* in_sizes, int n_in,
                              void* d_out, int out_size) {
    const float* x        = (const float*)d_in[0];
    const float* eps      = (const float*)d_in[1];
    const float* fcin_w   = (const float*)d_in[2];
    const float* fcin_b   = (const float*)d_in[3];
    const float* enc_wih  = (const float*)d_in[4];
    const float* enc_whh  = (const float*)d_in[5];
    const float* enc_bih  = (const float*)d_in[6];
    const float* enc_bhh  = (const float*)d_in[7];
    const float* mu_w     = (const float*)d_in[8];
    const float* mu_b     = (const float*)d_in[9];
    const float* lv_w     = (const float*)d_in[10];
    const float* lv_b     = (const float*)d_in[11];
    const float* din_w    = (const float*)d_in[12];
    const float* din_b    = (const float*)d_in[13];
    const float* dec_wih  = (const float*)d_in[14];
    const float* dec_whh  = (const float*)d_in[15];
    const float* dec_bih  = (const float*)d_in[16];
    const float* dec_bhh  = (const float*)d_in[17];
    const float* out_w    = (const float*)d_in[18];
    const float* out_b    = (const float*)d_in[19];
    float* out = (float*)d_out;

    cudaFuncSetAttribute(k_recur, cudaFuncAttributeMaxDynamicSharedMemorySize, SMEM_RECUR);
    cudaFuncSetAttribute(k_xg, cudaFuncAttributeMaxDynamicSharedMemorySize, SMEM_XG);

    k_ema<<<1, 512>>>(x);                                         // #1 (also resets)
    k_hin<<<dim3(Tz, Hz / 64), 256>>>(x, fcin_w, fcin_b);         // #2
    k_xg<<<dim3(Tz / 2, Z4z / 128), 256, SMEM_XG>>>(enc_wih, enc_bih, enc_bhh); // #3
    k_recur<<<64, 256, SMEM_RECUR>>>(enc_whh, 0);                 // #4 <- ncu capture
    k_latent<<<Bz, LATz>>>(mu_w, mu_b, lv_w, lv_b, eps, out);
    k_d<<<Bz, Hz>>>(din_w, din_b);
    k_xgdec<<<dim3(Bz, 4), 512>>>(dec_wih, dec_bih, dec_bhh);
    k_reset<<<129, 256>>>();
    k_recur<<<64, 256, SMEM_RECUR>>>(dec_whh, 1);
    k_out<<<Tz, 512>>>(out_w, out_b, out);
}